// round 11
// baseline (speedup 1.0000x reference)
#include <cuda_runtime.h>
#include <cuda_fp16.h>
#include <cstdint>

#define BATCH 4096
#define F 32
#define C 128
#define K1 32
#define K2 496
#define K3 4960
#define KTOT 5488
#define KPADH 5760              // 180 * 32, divisible by SPLITK*KB
#define KB 32                   // k per chunk = 2 fp16 mma k-steps of 16
#define NCH (KPADH / KB)        // 180
#define SPLITK 9
#define NCH_S (NCH / SPLITK)    // 20
#define TM 128
#define NT 256
#define NBX (BATCH / TM)        // 32
#define XT_STRIDE 132           // floats; 16B-aligned feature rows

// ---- smem byte layout ----
#define ABLK_BYTES 528                    // 512B fragment block + 16B pad
#define ABUF_BYTES (16 * ABLK_BYTES)      // 8448
#define WROW_BYTES 96                     // 64B data + 32B pad
#define WBUF_BYTES (128 * WROW_BYTES)     // 12288
#define SM_A0  0
#define SM_A1  ABUF_BYTES                 // 8448
#define SM_W0  (2 * ABUF_BYTES)           // 16896
#define SM_W1  (SM_W0 + WBUF_BYTES)       // 29184
#define SM_W2  (SM_W1 + WBUF_BYTES)       // 41472
#define SM_XS  (SM_W2 + WBUF_BYTES)       // 53760
#define SM_IDX (SM_XS + 33 * XT_STRIDE * 4)    // 71184
#define SMEM_BYTES (SM_IDX + NCH_S * KB * 4)   // 73744  -> 2 CTAs/SM

__device__ __half g_Wt[(size_t)C * KPADH];            // W^T, half, pair-permuted k
__device__ float g_scratch[(size_t)SPLITK * BATCH * C];
__device__ unsigned int g_cnt[NBX];                    // arrival counters (self-resetting)

__device__ __forceinline__ uint32_t smem_u32(const void* p) {
    return (uint32_t)__cvta_generic_to_shared(p);
}

__device__ __forceinline__ void mma_f16(float* c, const uint32_t* a, uint32_t b0, uint32_t b1) {
    asm volatile(
        "mma.sync.aligned.m16n8k16.row.col.f32.f16.f16.f32 "
        "{%0,%1,%2,%3}, {%4,%5,%6,%7}, {%8,%9}, {%0,%1,%2,%3};"
        : "+f"(c[0]), "+f"(c[1]), "+f"(c[2]), "+f"(c[3])
        : "r"(a[0]), "r"(a[1]), "r"(a[2]), "r"(a[3]), "r"(b0), "r"(b1));
}

__device__ __forceinline__ void cp16(uint32_t dst, const void* src) {
    asm volatile("cp.async.cg.shared.global [%0], [%1], 16;" :: "r"(dst), "l"(src) : "memory");
}

// position p in a 16-k block -> source k offset (inverse of the pair-permutation)
__device__ __forceinline__ int ksrc(int p) {   // p in [0,16)
    return (((p >> 1) & 1) << 3) + ((p >> 2) << 1) + (p & 1);
}

// ------- kernel 1: W -> g_Wt[c][perm(k)], half. One 32k x 128c tile per block. -------
__global__ void __launch_bounds__(512) transpose_W(
    const float* __restrict__ W1, const float* __restrict__ W2, const float* __restrict__ W3)
{
    __shared__ float t[32][129];
    const int kt = blockIdx.x * 32;
    const int tid = threadIdx.x;              // 512

    // load: 32 rows x 128 c = 1024 float4, 2 per thread, ALL issued before the sync
#pragma unroll
    for (int q = 0; q < 2; ++q) {
        int flat = tid + q * 512;
        int row = flat >> 5, c4 = flat & 31;
        int k = kt + row;
        float4 v = make_float4(0.f, 0.f, 0.f, 0.f);
        if (k < KTOT) {
            const float* p;
            if (k < K1)            p = W1 + (size_t)k * C;
            else if (k < K1 + K2)  p = W2 + (size_t)(k - K1) * C;
            else                   p = W3 + (size_t)(k - (K1 + K2)) * C;
            v = *reinterpret_cast<const float4*>(p + c4 * 4);
        }
        t[row][c4 * 4 + 0] = v.x;
        t[row][c4 * 4 + 1] = v.y;
        t[row][c4 * 4 + 2] = v.z;
        t[row][c4 * 4 + 3] = v.w;
    }
    __syncthreads();

    // store: thread = (c 0..127, h 0..3); h = (kb16, half) -> one 16B write
    {
        const int c    = tid & 127;
        const int kb16 = (tid >> 8) & 1;
        const int half = (tid >> 7) & 1;
        __half2 h2[4];
#pragma unroll
        for (int p2 = 0; p2 < 4; ++p2) {
            int pp = half * 8 + p2 * 2;
            float a = t[kb16 * 16 + ksrc(pp)][c];
            float b = t[kb16 * 16 + ksrc(pp + 1)][c];
            h2[p2] = __floats2half2_rn(a, b);
        }
        __half* dst = g_Wt + (size_t)c * KPADH + kt + kb16 * 16 + half * 8;
        *reinterpret_cast<uint4*>(dst) = *reinterpret_cast<uint4*>(h2);
    }
}

// ------- kernel 2: fp16 warp-mma GEMM + fused last-CTA split-K reduction -------
__global__ void __launch_bounds__(NT, 2) gemm_mma(
    const float* __restrict__ x,
    const int* __restrict__ idx1, const int* __restrict__ idx2, const int* __restrict__ idx3,
    const float* __restrict__ bias, float* __restrict__ out)
{
    extern __shared__ char smem[];
    float*    xs_t = (float*)(smem + SM_XS);       // [33][132]: xs_t[f][r]; f=32 -> ones
    uint32_t* idxs = (uint32_t*)(smem + SM_IDX);   // packed i0|i1<<8|i2<<16

    const int tid  = threadIdx.x;
    const int bx   = blockIdx.x;
    const int b0   = bx * TM;
    const int s    = blockIdx.y;
    const int lane = tid & 31;
    const int wid  = tid >> 5;
    const int gid  = lane >> 2;
    const int tg   = lane & 3;
    const int wm   = wid >> 1;
    const int wn   = wid & 1;

    // ---- x tile, transposed ----
    for (int t = tid; t < TM * (F / 4); t += NT) {
        int r = t >> 3, c4 = t & 7;
        float4 v = reinterpret_cast<const float4*>(x + (size_t)(b0 + r) * F)[c4];
        xs_t[(c4 * 4 + 0) * XT_STRIDE + r] = v.x;
        xs_t[(c4 * 4 + 1) * XT_STRIDE + r] = v.y;
        xs_t[(c4 * 4 + 2) * XT_STRIDE + r] = v.z;
        xs_t[(c4 * 4 + 3) * XT_STRIDE + r] = v.w;
    }
    if (tid < TM) xs_t[F * XT_STRIDE + tid] = 1.0f;

    // ---- packed index table for this split ----
    for (int e = tid; e < NCH_S * KB; e += NT) {
        int kg = s * NCH_S * KB + e;
        int i0 = F, i1 = F, i2 = F;
        if (kg < K1)            { i0 = idx1[kg]; }
        else if (kg < K1 + K2)  { const int* ip = idx2 + (size_t)(kg - K1) * 2;
                                  i0 = ip[0]; i1 = ip[1]; }
        else if (kg < KTOT)     { const int* ip = idx3 + (size_t)(kg - (K1 + K2)) * 3;
                                  i0 = ip[0]; i1 = ip[1]; i2 = ip[2]; }
        idxs[e] = (uint32_t)i0 | ((uint32_t)i1 << 8) | ((uint32_t)i2 << 16);
    }

    const int kp = tid & 15;
    const int r8 = tid >> 4;
    const int a_base_off = ((r8 >> 1) * 2 + (kp >> 3)) * 132
                         + (kp & 3) * 4 + (r8 & 1) + 2 * ((kp >> 2) & 1);

    __half2 pv[8];

    const uint32_t wsm[3] = { smem_u32(smem + SM_W0), smem_u32(smem + SM_W1),
                              smem_u32(smem + SM_W2) };
    const uint32_t asmb[2] = { SM_A0, SM_A1 };

    auto cp_W = [&](int c, uint32_t wbuf) {
        const int kbase = (s * NCH_S + c) * KB;
        const __half* src0 = g_Wt + kbase;
#pragma unroll
        for (int q = 0; q < 2; ++q) {
            int flat = tid + q * NT;
            int n = flat >> 2, i = flat & 3;
            cp16(wbuf + n * WROW_BYTES + i * 16, src0 + (size_t)n * KPADH + i * 8);
        }
    };

    auto products = [&](int c) {
        uint32_t u0 = idxs[c * KB + 2 * kp];
        uint32_t u1 = idxs[c * KB + 2 * kp + 1];
        const float* xa0 = xs_t + (u0 & 255) * XT_STRIDE + r8 * 8;
        const float* xa1 = xs_t + ((u0 >> 8) & 255) * XT_STRIDE + r8 * 8;
        const float* xa2 = xs_t + ((u0 >> 16) & 255) * XT_STRIDE + r8 * 8;
        const float* xb0 = xs_t + (u1 & 255) * XT_STRIDE + r8 * 8;
        const float* xb1 = xs_t + ((u1 >> 8) & 255) * XT_STRIDE + r8 * 8;
        const float* xb2 = xs_t + ((u1 >> 16) & 255) * XT_STRIDE + r8 * 8;
#pragma unroll
        for (int q = 0; q < 2; ++q) {
            float4 va0 = reinterpret_cast<const float4*>(xa0)[q];
            float4 va1 = reinterpret_cast<const float4*>(xa1)[q];
            float4 va2 = reinterpret_cast<const float4*>(xa2)[q];
            float4 vb0 = reinterpret_cast<const float4*>(xb0)[q];
            float4 vb1 = reinterpret_cast<const float4*>(xb1)[q];
            float4 vb2 = reinterpret_cast<const float4*>(xb2)[q];
            pv[q * 4 + 0] = __floats2half2_rn(va0.x * va1.x * va2.x, vb0.x * vb1.x * vb2.x);
            pv[q * 4 + 1] = __floats2half2_rn(va0.y * va1.y * va2.y, vb0.y * vb1.y * vb2.y);
            pv[q * 4 + 2] = __floats2half2_rn(va0.z * va1.z * va2.z, vb0.z * vb1.z * vb2.z);
            pv[q * 4 + 3] = __floats2half2_rn(va0.w * va1.w * va2.w, vb0.w * vb1.w * vb2.w);
        }
    };

    auto sts_products = [&](uint32_t abuf) {
#pragma unroll
        for (int j = 0; j < 8; ++j)
            *reinterpret_cast<__half2*>(smem + abuf + (uint32_t)(a_base_off + 16 * j) * 4) = pv[j];
    };

    float acc[2][8][4];
#pragma unroll
    for (int mb = 0; mb < 2; ++mb)
#pragma unroll
        for (int nb = 0; nb < 8; ++nb)
#pragma unroll
            for (int q = 0; q < 4; ++q) acc[mb][nb][q] = 0.0f;

    __syncthreads();                // xs_t + idx table ready

    cp_W(0, wsm[0]);
    asm volatile("cp.async.commit_group;" ::: "memory");
    cp_W(1, wsm[1]);
    asm volatile("cp.async.commit_group;" ::: "memory");
    products(0);
    sts_products(asmb[0]);
    asm volatile("cp.async.wait_group 1;" ::: "memory");   // W0 ready
    __syncthreads();

    for (int c = 0; c < NCH_S; ++c) {
        if (c + 2 < NCH_S) cp_W(c + 2, wsm[(c + 2) % 3]);
        asm volatile("cp.async.commit_group;" ::: "memory");

        if (c + 1 < NCH_S) products(c + 1);

        const char* Abuf = smem + asmb[c & 1];
        const char* Wbuf = smem + SM_W0 + (c % 3) * WBUF_BYTES;
#pragma unroll
        for (int ks = 0; ks < 2; ++ks) {
            uint32_t A[2][4];
#pragma unroll
            for (int mb = 0; mb < 2; ++mb) {
                uint4 v = *reinterpret_cast<const uint4*>(
                    Abuf + ((wm * 2 + mb) * 2 + ks) * ABLK_BYTES + lane * 16);
                A[mb][0] = v.x; A[mb][1] = v.y; A[mb][2] = v.z; A[mb][3] = v.w;
            }
#pragma unroll
            for (int nb = 0; nb < 8; ++nb) {
                uint2 b = *reinterpret_cast<const uint2*>(
                    Wbuf + (wn * 64 + nb * 8 + gid) * WROW_BYTES + ks * 32 + tg * 8);
                mma_f16(acc[0][nb], A[0], b.x, b.y);
                mma_f16(acc[1][nb], A[1], b.x, b.y);
            }
        }

        if (c + 1 < NCH_S) sts_products(asmb[(c + 1) & 1]);
        asm volatile("cp.async.wait_group 1;" ::: "memory");
        __syncthreads();
    }

    // ---- write deterministic split-K partial ----
    float* dst = g_scratch + ((size_t)s * BATCH + b0) * C;
#pragma unroll
    for (int mb = 0; mb < 2; ++mb) {
        int r = wm * 32 + mb * 16 + gid;
#pragma unroll
        for (int nb = 0; nb < 8; ++nb) {
            int col = wn * 64 + nb * 8 + 2 * tg;
            *reinterpret_cast<float2*>(dst + (size_t)r * C + col) =
                make_float2(acc[mb][nb][0], acc[mb][nb][1]);
            *reinterpret_cast<float2*>(dst + (size_t)(r + 8) * C + col) =
                make_float2(acc[mb][nb][2], acc[mb][nb][3]);
        }
    }

    // ---- fused reduction: last-arriving CTA for this bx sums all 9 partials ----
    __threadfence();                       // release partial
    __shared__ unsigned int s_old;
    if (tid == 0) s_old = atomicAdd(&g_cnt[bx], 1u);
    __syncthreads();
    if (s_old == SPLITK - 1) {
        __threadfence();                   // acquire all partials
        const int n4 = TM * C / 4;         // 4096 float4
        const float4* b4 = reinterpret_cast<const float4*>(bias);
        float4* o4 = reinterpret_cast<float4*>(out) + (size_t)b0 * (C / 4);
#pragma unroll 4
        for (int i = tid; i < n4; i += NT) {
            float4 b = b4[i & (C / 4 - 1)];
            float sx = b.x, sy = b.y, sz = b.z, sw = b.w;
#pragma unroll
            for (int ss = 0; ss < SPLITK; ss++) {
                float4 a = reinterpret_cast<const float4*>(
                    g_scratch + ((size_t)ss * BATCH + b0) * C)[i];
                sx += a.x; sy += a.y; sz += a.z; sw += a.w;
            }
            o4[i] = make_float4(sx, sy, sz, sw);
        }
        __syncthreads();
        if (tid == 0) g_cnt[bx] = 0;       // reset for next graph replay
    }
}

extern "C" void kernel_launch(void* const* d_in, const int* in_sizes, int n_in,
                              void* d_out, int out_size)
{
    const float* x    = (const float*)d_in[0];
    const float* bias = (const float*)d_in[1];
    const float* W1   = (const float*)d_in[2];
    const float* W2   = (const float*)d_in[3];
    const float* W3   = (const float*)d_in[4];
    const int*   idx1 = (const int*)d_in[5];
    const int*   idx2 = (const int*)d_in[6];
    const int*   idx3 = (const int*)d_in[7];
    float* out = (float*)d_out;

    static bool attr_set = false;
    if (!attr_set) {
        cudaFuncSetAttribute(gemm_mma, cudaFuncAttributeMaxDynamicSharedMemorySize, SMEM_BYTES);
        attr_set = true;
    }

    transpose_W<<<KPADH / 32, 512>>>(W1, W2, W3);
    gemm_mma<<<dim3(NBX, SPLITK), NT, SMEM_BYTES>>>(x, idx1, idx2, idx3, bias, out);
}

// round 13
// speedup vs baseline: 1.4134x; 1.4134x over previous
#include <cuda_runtime.h>
#include <cuda_fp16.h>
#include <cstdint>

#define BATCH 4096
#define F 32
#define C 128
#define K1 32
#define K2 496
#define K3 4960
#define KTOT 5488
#define KPADH 5760              // 180 * 32, divisible by SPLITK*KB
#define KB 32                   // k per chunk = 2 fp16 mma k-steps of 16
#define NCH (KPADH / KB)        // 180
#define SPLITK 9
#define NCH_S (NCH / SPLITK)    // 20
#define TM 128
#define NT 256
#define XTH_STRIDE 136          // halves; 272B per feature row (16B-aligned)

// ---- smem byte layout ----
#define ABLK_BYTES 528                    // 512B fragment block + 16B pad
#define ABUF_BYTES (16 * ABLK_BYTES)      // 8448
#define WROW_BYTES 96                     // 64B data + 32B pad
#define WBUF_BYTES (128 * WROW_BYTES)     // 12288
#define SM_A0  0
#define SM_A1  ABUF_BYTES                 // 8448
#define SM_W0  (2 * ABUF_BYTES)           // 16896
#define SM_W1  (SM_W0 + WBUF_BYTES)       // 29184
#define SM_W2  (SM_W1 + WBUF_BYTES)       // 41472
#define SM_XS  (SM_W2 + WBUF_BYTES)       // 53760
#define SM_IDX (SM_XS + 33 * XTH_STRIDE * 2)   // 62736
#define SMEM_BYTES (SM_IDX + NCH_S * KB * 4)   // 65296  -> 2 CTAs/SM

__device__ __half g_Wt[(size_t)C * KPADH];            // W^T, half, pair-permuted k
__device__ float g_scratch[(size_t)SPLITK * BATCH * C];

__device__ __forceinline__ uint32_t smem_u32(const void* p) {
    return (uint32_t)__cvta_generic_to_shared(p);
}

__device__ __forceinline__ void mma_f16(float* c, const uint32_t* a, uint32_t b0, uint32_t b1) {
    asm volatile(
        "mma.sync.aligned.m16n8k16.row.col.f32.f16.f16.f32 "
        "{%0,%1,%2,%3}, {%4,%5,%6,%7}, {%8,%9}, {%0,%1,%2,%3};"
        : "+f"(c[0]), "+f"(c[1]), "+f"(c[2]), "+f"(c[3])
        : "r"(a[0]), "r"(a[1]), "r"(a[2]), "r"(a[3]), "r"(b0), "r"(b1));
}

__device__ __forceinline__ void cp16(uint32_t dst, const void* src) {
    asm volatile("cp.async.cg.shared.global [%0], [%1], 16;" :: "r"(dst), "l"(src) : "memory");
}

// position p in a 16-k block -> source k offset (inverse of the pair-permutation)
__device__ __forceinline__ int ksrc(int p) {   // p in [0,16)
    return (((p >> 1) & 1) << 3) + ((p >> 2) << 1) + (p & 1);
}

// ------- kernel 1: W -> g_Wt[c][perm(k)], half. One 32k x 128c tile per block. -------
__global__ void __launch_bounds__(512) transpose_W(
    const float* __restrict__ W1, const float* __restrict__ W2, const float* __restrict__ W3)
{
    __shared__ float t[32][129];
    const int kt = blockIdx.x * 32;
    const int tid = threadIdx.x;              // 512

#pragma unroll
    for (int q = 0; q < 2; ++q) {
        int flat = tid + q * 512;
        int row = flat >> 5, c4 = flat & 31;
        int k = kt + row;
        float4 v = make_float4(0.f, 0.f, 0.f, 0.f);
        if (k < KTOT) {
            const float* p;
            if (k < K1)            p = W1 + (size_t)k * C;
            else if (k < K1 + K2)  p = W2 + (size_t)(k - K1) * C;
            else                   p = W3 + (size_t)(k - (K1 + K2)) * C;
            v = *reinterpret_cast<const float4*>(p + c4 * 4);
        }
        t[row][c4 * 4 + 0] = v.x;
        t[row][c4 * 4 + 1] = v.y;
        t[row][c4 * 4 + 2] = v.z;
        t[row][c4 * 4 + 3] = v.w;
    }
    __syncthreads();

    {
        const int c    = tid & 127;
        const int kb16 = (tid >> 8) & 1;
        const int half = (tid >> 7) & 1;
        __half2 h2[4];
#pragma unroll
        for (int p2 = 0; p2 < 4; ++p2) {
            int pp = half * 8 + p2 * 2;
            float a = t[kb16 * 16 + ksrc(pp)][c];
            float b = t[kb16 * 16 + ksrc(pp + 1)][c];
            h2[p2] = __floats2half2_rn(a, b);
        }
        __half* dst = g_Wt + (size_t)c * KPADH + kt + kb16 * 16 + half * 8;
        *reinterpret_cast<uint4*>(dst) = *reinterpret_cast<uint4*>(h2);
    }
}

// ------- kernel 2: fp16 warp-mma GEMM, P computed from fp16 x tile -------
__global__ void __launch_bounds__(NT, 2) gemm_mma(
    const float* __restrict__ x,
    const int* __restrict__ idx1, const int* __restrict__ idx2, const int* __restrict__ idx3)
{
    extern __shared__ char smem[];
    __half*   xsh  = (__half*)(smem + SM_XS);      // [33][136]: xsh[f][r]; f=32 -> ones
    uint32_t* idxs = (uint32_t*)(smem + SM_IDX);   // packed i0|i1<<8|i2<<16

    const int tid  = threadIdx.x;
    const int b0   = blockIdx.x * TM;
    const int s    = blockIdx.y;
    const int lane = tid & 31;
    const int wid  = tid >> 5;
    const int gid  = lane >> 2;
    const int tg   = lane & 3;
    const int wm   = wid >> 1;
    const int wn   = wid & 1;

    // ---- x tile, transposed, fp16 ----
    for (int t = tid; t < TM * (F / 4); t += NT) {
        int r = t >> 3, c4 = t & 7;
        float4 v = reinterpret_cast<const float4*>(x + (size_t)(b0 + r) * F)[c4];
        xsh[(c4 * 4 + 0) * XTH_STRIDE + r] = __float2half_rn(v.x);
        xsh[(c4 * 4 + 1) * XTH_STRIDE + r] = __float2half_rn(v.y);
        xsh[(c4 * 4 + 2) * XTH_STRIDE + r] = __float2half_rn(v.z);
        xsh[(c4 * 4 + 3) * XTH_STRIDE + r] = __float2half_rn(v.w);
    }
    if (tid < TM) xsh[F * XTH_STRIDE + tid] = __float2half_rn(1.0f);

    // ---- packed index table for this split (built once) ----
    for (int e = tid; e < NCH_S * KB; e += NT) {
        int kg = s * NCH_S * KB + e;
        int i0 = F, i1 = F, i2 = F;
        if (kg < K1)            { i0 = idx1[kg]; }
        else if (kg < K1 + K2)  { const int* ip = idx2 + (size_t)(kg - K1) * 2;
                                  i0 = ip[0]; i1 = ip[1]; }
        else if (kg < KTOT)     { const int* ip = idx3 + (size_t)(kg - (K1 + K2)) * 3;
                                  i0 = ip[0]; i1 = ip[1]; i2 = ip[2]; }
        idxs[e] = (uint32_t)i0 | ((uint32_t)i1 << 8) | ((uint32_t)i2 << 16);
    }

    // staging roles: thread = (k-pair kp, row-group r8)
    const int kp = tid & 15;
    const int r8 = tid >> 4;
    const int a_base_off = ((r8 >> 1) * 2 + (kp >> 3)) * 132
                         + (kp & 3) * 4 + (r8 & 1) + 2 * ((kp >> 2) & 1);

    __half2 pv[8];

    const uint32_t wsm[3] = { smem_u32(smem + SM_W0), smem_u32(smem + SM_W1),
                              smem_u32(smem + SM_W2) };
    const uint32_t asmb[2] = { SM_A0, SM_A1 };

    auto cp_W = [&](int c, uint32_t wbuf) {
        const int kbase = (s * NCH_S + c) * KB;
        const __half* src0 = g_Wt + kbase;
#pragma unroll
        for (int q = 0; q < 2; ++q) {
            int flat = tid + q * NT;
            int n = flat >> 2, i = flat & 3;
            cp16(wbuf + n * WROW_BYTES + i * 16, src0 + (size_t)n * KPADH + i * 8);
        }
    };

    auto products = [&](int c) {
        uint32_t u0 = idxs[c * KB + 2 * kp];
        uint32_t u1 = idxs[c * KB + 2 * kp + 1];
        // 6 feature-row gathers: 8 rows x 2B = one 16B load each
        const uint4 va0 = *reinterpret_cast<const uint4*>(xsh + (u0 & 255) * XTH_STRIDE + r8 * 8);
        const uint4 va1 = *reinterpret_cast<const uint4*>(xsh + ((u0 >> 8) & 255) * XTH_STRIDE + r8 * 8);
        const uint4 va2 = *reinterpret_cast<const uint4*>(xsh + ((u0 >> 16) & 255) * XTH_STRIDE + r8 * 8);
        const uint4 vb0 = *reinterpret_cast<const uint4*>(xsh + (u1 & 255) * XTH_STRIDE + r8 * 8);
        const uint4 vb1 = *reinterpret_cast<const uint4*>(xsh + ((u1 >> 8) & 255) * XTH_STRIDE + r8 * 8);
        const uint4 vb2 = *reinterpret_cast<const uint4*>(xsh + ((u1 >> 16) & 255) * XTH_STRIDE + r8 * 8);
        const __half2* a0 = reinterpret_cast<const __half2*>(&va0);
        const __half2* a1 = reinterpret_cast<const __half2*>(&va1);
        const __half2* a2 = reinterpret_cast<const __half2*>(&va2);
        const __half2* b0 = reinterpret_cast<const __half2*>(&vb0);
        const __half2* b1 = reinterpret_cast<const __half2*>(&vb1);
        const __half2* b2 = reinterpret_cast<const __half2*>(&vb2);
#pragma unroll
        for (int i = 0; i < 4; ++i) {
            __half2 q0 = __hmul2(__hmul2(a0[i], a1[i]), a2[i]);   // rows 2i,2i+1 @ k0
            __half2 q1 = __hmul2(__hmul2(b0[i], b1[i]), b2[i]);   // rows 2i,2i+1 @ k1
            pv[2 * i]     = __lows2half2(q0, q1);                 // (P[k0][2i],   P[k1][2i])
            pv[2 * i + 1] = __highs2half2(q0, q1);                // (P[k0][2i+1], P[k1][2i+1])
        }
    };

    auto sts_products = [&](uint32_t abuf) {
#pragma unroll
        for (int j = 0; j < 8; ++j)
            *reinterpret_cast<__half2*>(smem + abuf + (uint32_t)(a_base_off + 16 * j) * 4) = pv[j];
    };

    float acc[2][8][4];
#pragma unroll
    for (int mb = 0; mb < 2; ++mb)
#pragma unroll
        for (int nb = 0; nb < 8; ++nb)
#pragma unroll
            for (int q = 0; q < 4; ++q) acc[mb][nb][q] = 0.0f;

    __syncthreads();                // xsh + idx table ready

    cp_W(0, wsm[0]);
    asm volatile("cp.async.commit_group;" ::: "memory");
    cp_W(1, wsm[1]);
    asm volatile("cp.async.commit_group;" ::: "memory");
    products(0);
    sts_products(asmb[0]);
    asm volatile("cp.async.wait_group 1;" ::: "memory");   // W0 ready
    __syncthreads();

    for (int c = 0; c < NCH_S; ++c) {
        if (c + 2 < NCH_S) cp_W(c + 2, wsm[(c + 2) % 3]);
        asm volatile("cp.async.commit_group;" ::: "memory");

        if (c + 1 < NCH_S) products(c + 1);

        const char* Abuf = smem + asmb[c & 1];
        const char* Wbuf = smem + SM_W0 + (c % 3) * WBUF_BYTES;
#pragma unroll
        for (int ks = 0; ks < 2; ++ks) {
            uint32_t A[2][4];
#pragma unroll
            for (int mb = 0; mb < 2; ++mb) {
                uint4 v = *reinterpret_cast<const uint4*>(
                    Abuf + ((wm * 2 + mb) * 2 + ks) * ABLK_BYTES + lane * 16);
                A[mb][0] = v.x; A[mb][1] = v.y; A[mb][2] = v.z; A[mb][3] = v.w;
            }
#pragma unroll
            for (int nb = 0; nb < 8; ++nb) {
                uint2 b = *reinterpret_cast<const uint2*>(
                    Wbuf + (wn * 64 + nb * 8 + gid) * WROW_BYTES + ks * 32 + tg * 8);
                mma_f16(acc[0][nb], A[0], b.x, b.y);
                mma_f16(acc[1][nb], A[1], b.x, b.y);
            }
        }

        if (c + 1 < NCH_S) sts_products(asmb[(c + 1) & 1]);
        asm volatile("cp.async.wait_group 1;" ::: "memory");
        __syncthreads();
    }

    // ---- epilogue: deterministic split-K partials ----
    float* dst = g_scratch + ((size_t)s * BATCH + b0) * C;
#pragma unroll
    for (int mb = 0; mb < 2; ++mb) {
        int r = wm * 32 + mb * 16 + gid;
#pragma unroll
        for (int nb = 0; nb < 8; ++nb) {
            int col = wn * 64 + nb * 8 + 2 * tg;
            *reinterpret_cast<float2*>(dst + (size_t)r * C + col) =
                make_float2(acc[mb][nb][0], acc[mb][nb][1]);
            *reinterpret_cast<float2*>(dst + (size_t)(r + 8) * C + col) =
                make_float2(acc[mb][nb][2], acc[mb][nb][3]);
        }
    }
}

// ---------------- kernel 3: split-K reduce + bias ----------------
__global__ void reduce_out(const float* __restrict__ bias, float* __restrict__ out)
{
    const int n4 = BATCH * C / 4;
    int i = blockIdx.x * blockDim.x + threadIdx.x;
    if (i < n4) {
        float4 b = reinterpret_cast<const float4*>(bias)[i & (C / 4 - 1)];
        float sx = b.x, sy = b.y, sz = b.z, sw = b.w;
#pragma unroll
        for (int s = 0; s < SPLITK; s++) {
            float4 a = reinterpret_cast<const float4*>(g_scratch + (size_t)s * BATCH * C)[i];
            sx += a.x; sy += a.y; sz += a.z; sw += a.w;
        }
        reinterpret_cast<float4*>(out)[i] = make_float4(sx, sy, sz, sw);
    }
}

extern "C" void kernel_launch(void* const* d_in, const int* in_sizes, int n_in,
                              void* d_out, int out_size)
{
    const float* x    = (const float*)d_in[0];
    const float* bias = (const float*)d_in[1];
    const float* W1   = (const float*)d_in[2];
    const float* W2   = (const float*)d_in[3];
    const float* W3   = (const float*)d_in[4];
    const int*   idx1 = (const int*)d_in[5];
    const int*   idx2 = (const int*)d_in[6];
    const int*   idx3 = (const int*)d_in[7];
    float* out = (float*)d_out;

    static bool attr_set = false;
    if (!attr_set) {
        cudaFuncSetAttribute(gemm_mma, cudaFuncAttributeMaxDynamicSharedMemorySize, SMEM_BYTES);
        attr_set = true;
    }

    transpose_W<<<KPADH / 32, 512>>>(W1, W2, W3);
    gemm_mma<<<dim3(BATCH / TM, SPLITK), NT, SMEM_BYTES>>>(x, idx1, idx2, idx3);

    int n4 = BATCH * C / 4;
    reduce_out<<<n4 / 256, 256>>>(bias, out);
}